// round 12
// baseline (speedup 1.0000x reference)
#include <cuda_runtime.h>
#include <cuda_fp16.h>
#include <math.h>
#include <stdint.h>

#define Pp 16384
#define Dd 128
#define Bb 4
#define Nn 6
#define Mm 65536   // B*P rows
#define NSM 148

// ---- scratch (static device globals; no allocation allowed) ----
__device__ __half  refTh_g[(size_t)Bb * Nn * Pp * Dd]; // (bn, p, d) fp16
__device__ float   qT_g[(size_t)Bb * Pp * Dd];         // (bp, d) fp32
__device__ float   ztLN_g[(size_t)Bb * Pp * Dd];       // (bp, d) fp32 (residual)
__device__ __half  ztLNh_g[(size_t)Mm * Dd];           // fp16 copy for GEMM1
__device__ __half  hbufh_g[(size_t)Mm * 256];          // gelu output fp16
__device__ __half  W1h_g[256 * 128];                   // [n][k] fp16
__device__ __half  W2h_g[128 * 256];                   // [n][k] fp16

// ---------------------------------------------------------------
// helpers
// ---------------------------------------------------------------
__device__ __forceinline__ float wsum16(float v) {
#pragma unroll
    for (int s = 1; s < 16; s <<= 1) v += __shfl_xor_sync(0xffffffffu, v, s);
    return v;
}
__device__ __forceinline__ float gelu_exact(float x) {
    return 0.5f * x * (1.0f + erff(x * 0.70710678118654752440f));
}
__device__ __forceinline__ void h8_to_f8(uint4 u, float* f) {
    float2 t;
    t = __half22float2(*reinterpret_cast<__half2*>(&u.x)); f[0] = t.x; f[1] = t.y;
    t = __half22float2(*reinterpret_cast<__half2*>(&u.y)); f[2] = t.x; f[3] = t.y;
    t = __half22float2(*reinterpret_cast<__half2*>(&u.z)); f[4] = t.x; f[5] = t.y;
    t = __half22float2(*reinterpret_cast<__half2*>(&u.w)); f[6] = t.x; f[7] = t.y;
}
__device__ __forceinline__ uint32_t smem_u32(const void* p) {
    uint32_t a;
    asm("{ .reg .u64 t; cvta.to.shared.u64 t, %1; cvt.u32.u64 %0, t; }" : "=r"(a) : "l"(p));
    return a;
}

#define LDSM_X4(r0, r1, r2, r3, a) \
    asm volatile("ldmatrix.sync.aligned.m8n8.x4.shared.b16 {%0,%1,%2,%3}, [%4];" \
                 : "=r"(r0), "=r"(r1), "=r"(r2), "=r"(r3) : "r"(a))
#define LDSM_X2(r0, r1, a) \
    asm volatile("ldmatrix.sync.aligned.m8n8.x2.shared.b16 {%0,%1}, [%2];" \
                 : "=r"(r0), "=r"(r1) : "r"(a))
#define MMA16816(d, a, b) \
    asm volatile("mma.sync.aligned.m16n8k16.row.col.f32.f16.f16.f32 " \
                 "{%0,%1,%2,%3}, {%4,%5,%6,%7}, {%8,%9}, {%0,%1,%2,%3};" \
                 : "+f"((d)[0]), "+f"((d)[1]), "+f"((d)[2]), "+f"((d)[3]) \
                 : "r"((a)[0]), "r"((a)[1]), "r"((a)[2]), "r"((a)[3]), \
                   "r"((b)[0]), "r"((b)[1]))

#define APITCH 136   // halves per smem row (128 + 8 pad -> conflict-free ldmatrix)
#define HTILE  (128 * APITCH)   // halves per 128x128 padded tile (17408)

// ---------------------------------------------------------------
// Merged prep: z<24 -> ref transpose to fp16; z in [24,28) -> q transpose
// to fp32; z==28 -> weight conversion.
// ---------------------------------------------------------------
__global__ void __launch_bounds__(256) prep_all_kernel(const float* __restrict__ ref,
                                                       const float* __restrict__ query,
                                                       const float* __restrict__ W1,
                                                       const float* __restrict__ W2) {
    int z = blockIdx.z;
    if (z == 28) {
        int idx = blockIdx.x * 256 + threadIdx.x;
        if (idx < 32768) {
            int n = idx >> 7, k = idx & 127;
            W1h_g[idx] = __float2half(W1[(size_t)k * 256 + n]);
        } else if (idx < 65536) {
            int j = idx - 32768;
            int n = j >> 8, k = j & 255;
            W2h_g[j] = __float2half(W2[(size_t)k * 128 + n]);
        }
        return;
    }

    __shared__ float tile[32][129];
    int p0 = blockIdx.x * 32;
    int lane = threadIdx.x & 31;
    int ty = threadIdx.x >> 5;

    if (z < 24) {
        const float* src = ref + (size_t)z * Dd * Pp;
        __half* dst = refTh_g + (size_t)z * Pp * Dd;
#pragma unroll
        for (int it = 0; it < 16; it++) {
            int d = it * 8 + ty;
            tile[lane][d] = src[(size_t)d * Pp + p0 + lane];
        }
        __syncthreads();
        int pi = threadIdx.x & 63;
        int ppb = threadIdx.x >> 6;
#pragma unroll
        for (int it = 0; it < 8; it++) {
            int pp = it * 4 + ppb;
            float2 f = make_float2(tile[pp][2 * pi], tile[pp][2 * pi + 1]);
            *(__half2*)(dst + (size_t)(p0 + pp) * Dd + 2 * pi) = __float22half2_rn(f);
        }
    } else {
        int mat = z - 24;
        const float* src = query + (size_t)mat * Dd * Pp;
        float* dst = qT_g + (size_t)mat * Dd * Pp;
#pragma unroll
        for (int it = 0; it < 16; it++) {
            int d = it * 8 + ty;
            tile[lane][d] = src[(size_t)d * Pp + p0 + lane];
        }
        __syncthreads();
#pragma unroll
        for (int it = 0; it < 16; it++) {
            int idx = it * 256 + threadIdx.x;
            int pp = idx >> 7, d = idx & 127;
            dst[(size_t)(p0 + pp) * Dd + d] = tile[pp][d];
        }
    }
}

// ---------------------------------------------------------------
// Attention: 2 pixels/warp, 16 lanes/pixel, 8 ch/lane, 4 CTAs/SM.
// (unchanged from R9-best)
// ---------------------------------------------------------------
__global__ void __launch_bounds__(256, 4) attn_kernel(const float* __restrict__ homo,
                                                      const float* __restrict__ ln1w,
                                                      const float* __restrict__ ln1b) {
    int lane = threadIdx.x & 31;
    int warp = threadIdx.x >> 5;
    int sub = lane >> 4;
    int sl = lane & 15;
    int gp = blockIdx.x * 16 + warp * 2 + sub;
    int b = gp >> 14;
    int p = gp & (Pp - 1);

    float us[6], vs[6];
#pragma unroll
    for (int n = 0; n < 6; n++) {
        int bn = b * Nn + n;
        us[n] = homo[(size_t)(bn * 2 + 0) * Pp + p] * 128.0f;
        vs[n] = homo[(size_t)(bn * 2 + 1) * Pp + p] * 128.0f;
    }

    float q[8];
    {
        float4 q0 = *(const float4*)(qT_g + (size_t)gp * Dd + sl * 8);
        float4 q1 = *(const float4*)(qT_g + (size_t)gp * Dd + sl * 8 + 4);
        q[0] = q0.x; q[1] = q0.y; q[2] = q0.z; q[3] = q0.w;
        q[4] = q1.x; q[5] = q1.y; q[6] = q1.z; q[7] = q1.w;
    }
    float qn2 = 0.0f;
#pragma unroll
    for (int k = 0; k < 8; k++) qn2 += q[k] * q[k];
    qn2 = wsum16(qn2);
    float qden = fmaxf(sqrtf(qn2), 1e-12f);

    __half2 vh[6][4];
    float dots[6];

#pragma unroll
    for (int n = 0; n < 6; n++) {
        int bn = b * Nn + n;
        float u = us[n], v = vs[n];
        float wx = u - floorf(u), wy = v - floorf(v);
        int ix0 = min(max(__float2int_rd(u), 0), 127);
        int ix1 = min(max(__float2int_rd(u) + 1, 0), 127);
        int iy0 = min(max(__float2int_rd(v), 0), 127);
        int iy1 = min(max(__float2int_rd(v) + 1, 0), 127);
        bool valid = (u >= 0.0f) && (u <= 127.0f) && (v >= 0.0f) && (v <= 127.0f);

        const __half* base = refTh_g + (size_t)bn * Pp * Dd + sl * 8;
        uint4 r00 = *(const uint4*)(base + ((iy0 << 7) + ix0) * Dd);
        uint4 r10 = *(const uint4*)(base + ((iy0 << 7) + ix1) * Dd);
        uint4 r01 = *(const uint4*)(base + ((iy1 << 7) + ix0) * Dd);
        uint4 r11 = *(const uint4*)(base + ((iy1 << 7) + ix1) * Dd);

        float c00[8], c10[8], c01[8], c11[8];
        h8_to_f8(r00, c00); h8_to_f8(r10, c10);
        h8_to_f8(r01, c01); h8_to_f8(r11, c11);

        float w00 = (1.0f - wx) * (1.0f - wy);
        float w10 = wx * (1.0f - wy);
        float w01 = (1.0f - wx) * wy;
        float w11 = wx * wy;

        float v2 = 0.0f, s = 0.0f;
#pragma unroll
        for (int k = 0; k < 8; k += 2) {
            float val0 = w00 * c00[k] + w10 * c10[k] + w01 * c01[k] + w11 * c11[k];
            float val1 = w00 * c00[k + 1] + w10 * c10[k + 1] + w01 * c01[k + 1] + w11 * c11[k + 1];
            vh[n][k >> 1] = __floats2half2_rn(val0, val1);
            v2 += val0 * val0 + val1 * val1;
            s += q[k] * val0 + q[k + 1] * val1;
        }
        v2 = wsum16(v2);
        s = wsum16(s);
        float vden = fmaxf(sqrtf(v2), 1e-12f);
        dots[n] = valid ? __fdividef(s, qden * vden) : 0.0f;
    }

    float m = dots[0];
#pragma unroll
    for (int n = 1; n < 6; n++) m = fmaxf(m, dots[n]);
    float e[6], esum = 0.0f;
#pragma unroll
    for (int n = 0; n < 6; n++) { e[n] = __expf(dots[n] - m); esum += e[n]; }
    float inv = __fdividef(1.0f, esum);

#pragma unroll
    for (int k2 = 0; k2 < 4; k2++) {
        float zx = 0.0f, zy = 0.0f;
#pragma unroll
        for (int n = 0; n < 6; n++) {
            float2 vv = __half22float2(vh[n][k2]);
            zx += e[n] * vv.x;
            zy += e[n] * vv.y;
        }
        q[2 * k2] += zx * inv;
        q[2 * k2 + 1] += zy * inv;
    }

    float ssum = 0.0f;
#pragma unroll
    for (int k = 0; k < 8; k++) ssum += q[k];
    float mean = wsum16(ssum) * (1.0f / 128.0f);
    float dv = 0.0f;
#pragma unroll
    for (int k = 0; k < 8; k++) { float dd = q[k] - mean; dv += dd * dd; }
    float rstd = rsqrtf(wsum16(dv) * (1.0f / 128.0f) + 1e-5f);

    float o[8];
    {
        float4 lw0 = *(const float4*)(ln1w + sl * 8);
        float4 lw1 = *(const float4*)(ln1w + sl * 8 + 4);
        float4 lb0 = *(const float4*)(ln1b + sl * 8);
        float4 lb1 = *(const float4*)(ln1b + sl * 8 + 4);
        o[0] = (q[0] - mean) * rstd * lw0.x + lb0.x;
        o[1] = (q[1] - mean) * rstd * lw0.y + lb0.y;
        o[2] = (q[2] - mean) * rstd * lw0.z + lb0.z;
        o[3] = (q[3] - mean) * rstd * lw0.w + lb0.w;
        o[4] = (q[4] - mean) * rstd * lw1.x + lb1.x;
        o[5] = (q[5] - mean) * rstd * lw1.y + lb1.y;
        o[6] = (q[6] - mean) * rstd * lw1.z + lb1.z;
        o[7] = (q[7] - mean) * rstd * lw1.w + lb1.w;
    }
    float* dstf = ztLN_g + (size_t)gp * Dd + sl * 8;
    *(float4*)dstf = make_float4(o[0], o[1], o[2], o[3]);
    *(float4*)(dstf + 4) = make_float4(o[4], o[5], o[6], o[7]);

    __half2 h[4];
    h[0] = __floats2half2_rn(o[0], o[1]);
    h[1] = __floats2half2_rn(o[2], o[3]);
    h[2] = __floats2half2_rn(o[4], o[5]);
    h[3] = __floats2half2_rn(o[6], o[7]);
    *(float4*)(ztLNh_g + (size_t)gp * Dd + sl * 8) = *(float4*)h;
}

// ---------------------------------------------------------------
// GEMM1 persistent (mma.sync): H = gelu(ztLNh @ W1 + b1).
// grid=148, 512 threads (16 warps 4x4), BM=128, W1 resident in smem.
// ---------------------------------------------------------------
#define G1_SMEM (HTILE * 2 + 2 * HTILE * 2)   // A(34816B) + B(69632B) = 104448
__global__ void __launch_bounds__(512) gemm1_mma(const float* __restrict__ b1) {
    extern __shared__ __half sm1[];
    __half* Ah = sm1;                 // 128 x APITCH
    __half* Bh = sm1 + HTILE;         // 256 x APITCH
    uint32_t Abase = smem_u32(Ah), Bbase = smem_u32(Bh);

    int tid = threadIdx.x;
    int warp = tid >> 5, lane = tid & 31;

    // B fill once: W1h 256x128
    for (int idx = tid; idx < 4096; idx += 512) {
        int r = idx >> 4, kg = (idx & 15) << 3;
        *(float4*)(Bh + r * APITCH + kg) =
            *(const float4*)(W1h_g + (size_t)r * 128 + kg);
    }

    int warp_m = warp & 3, warp_n = warp >> 2;
    int rm = warp_m * 32;
    int arow = (lane & 7) + ((lane >> 3) & 1) * 8;
    int akol = (lane >> 4) * 8;
    int brow = lane & 7;
    int bkol = ((lane >> 3) & 1) * 8;
    int qrow = lane >> 2, qcol = (lane & 3) * 2;

    for (int t = blockIdx.x; t < Mm / 128; t += NSM) {
        int rowBase = t << 7;
        for (int idx = tid; idx < 2048; idx += 512) {
            int r = idx >> 4, kg = (idx & 15) << 3;
            *(float4*)(Ah + r * APITCH + kg) =
                *(const float4*)(ztLNh_g + (size_t)(rowBase + r) * 128 + kg);
        }
        __syncthreads();

#pragma unroll
        for (int nh = 0; nh < 2; nh++) {
            int cn = nh * 128 + warp_n * 32;
            float acc[2][4][4] = {};
#pragma unroll
            for (int ks = 0; ks < 8; ks++) {
                int k0 = ks * 16;
                uint32_t a[2][4], bf[4][2];
#pragma unroll
                for (int mt = 0; mt < 2; mt++)
                    LDSM_X4(a[mt][0], a[mt][1], a[mt][2], a[mt][3],
                            Abase + ((rm + mt * 16 + arow) * APITCH + k0 + akol) * 2);
#pragma unroll
                for (int nt = 0; nt < 4; nt++)
                    LDSM_X2(bf[nt][0], bf[nt][1],
                            Bbase + ((cn + nt * 8 + brow) * APITCH + k0 + bkol) * 2);
#pragma unroll
                for (int mt = 0; mt < 2; mt++)
#pragma unroll
                    for (int nt = 0; nt < 4; nt++)
                        MMA16816(acc[mt][nt], a[mt], bf[nt]);
            }

#pragma unroll
            for (int nt = 0; nt < 4; nt++) {
                int col = cn + nt * 8 + qcol;
                float bx = __ldg(b1 + col), by = __ldg(b1 + col + 1);
#pragma unroll
                for (int mt = 0; mt < 2; mt++) {
                    int row = rowBase + rm + mt * 16 + qrow;
                    __half2 h0 = __floats2half2_rn(gelu_exact(acc[mt][nt][0] + bx),
                                                   gelu_exact(acc[mt][nt][1] + by));
                    __half2 h1 = __floats2half2_rn(gelu_exact(acc[mt][nt][2] + bx),
                                                   gelu_exact(acc[mt][nt][3] + by));
                    *(__half2*)(hbufh_g + (size_t)row * 256 + col) = h0;
                    *(__half2*)(hbufh_g + (size_t)(row + 8) * 256 + col) = h1;
                }
            }
        }
        __syncthreads();   // A reads done before next tile's fill
    }
}

// ---------------------------------------------------------------
// GEMM2 persistent (mma.sync): zt2 = ztLN + hbufh @ W2 + b2; LN2;
// transposed store. grid=148, 512 threads, BM=128, W2 resident.
// smem: A0,A1,B0,B1 (4 x 34816B) + red (4KB). Staging reuses A region.
// ---------------------------------------------------------------
#define G2_SMEM (4 * HTILE * 2 + 4096)   // 143360
#define STGP 132
__global__ void __launch_bounds__(512) gemm2_mma(const float* __restrict__ b2,
                                                 const float* __restrict__ ln2w,
                                                 const float* __restrict__ ln2b,
                                                 float* __restrict__ out) {
    extern __shared__ __half sm2[];
    __half* A0 = sm2;
    __half* A1 = sm2 + HTILE;
    __half* B0 = sm2 + 2 * HTILE;
    __half* B1 = sm2 + 3 * HTILE;
    float* redS = (float*)(sm2 + 4 * HTILE);   // [128][4]
    float* redQ = redS + 512;                  // [128][4]
    float* stg  = (float*)sm2;                 // [128 cols][STGP] reuses A0+A1
    uint32_t A0b = smem_u32(A0), A1b = smem_u32(A1);
    uint32_t B0b = smem_u32(B0), B1b = smem_u32(B1);

    int tid = threadIdx.x;
    int warp = tid >> 5, lane = tid & 31;

    // B fill once: W2h [128 n][256 k] -> two 128x128 chunks
    for (int idx = tid; idx < 2048; idx += 512) {
        int r = idx >> 4, kg = (idx & 15) << 3;
        *(float4*)(B0 + r * APITCH + kg) =
            *(const float4*)(W2h_g + (size_t)r * 256 + kg);
        *(float4*)(B1 + r * APITCH + kg) =
            *(const float4*)(W2h_g + (size_t)r * 256 + 128 + kg);
    }

    int warp_m = warp & 3, warp_n = warp >> 2;
    int rm = warp_m * 32, cn = warp_n * 32;
    int arow = (lane & 7) + ((lane >> 3) & 1) * 8;
    int akol = (lane >> 4) * 8;
    int brow = lane & 7;
    int bkol = ((lane >> 3) & 1) * 8;
    int qrow = lane >> 2, qcol = (lane & 3) * 2;

    for (int t = blockIdx.x; t < Mm / 128; t += NSM) {
        int rowBase = t << 7;

        // A fill: 128 rows x 256 k -> A0 (k<128) + A1 (k>=128)
        for (int idx = tid; idx < 2048; idx += 512) {
            int r = idx >> 4, kg = (idx & 15) << 3;
            *(float4*)(A0 + r * APITCH + kg) =
                *(const float4*)(hbufh_g + (size_t)(rowBase + r) * 256 + kg);
            *(float4*)(A1 + r * APITCH + kg) =
                *(const float4*)(hbufh_g + (size_t)(rowBase + r) * 256 + 128 + kg);
        }
        __syncthreads();

        float acc[2][4][4] = {};
#pragma unroll
        for (int kc = 0; kc < 2; kc++) {
            uint32_t Ab_ = kc ? A1b : A0b;
            uint32_t Bb_ = kc ? B1b : B0b;
#pragma unroll
            for (int ks = 0; ks < 8; ks++) {
                int k0 = ks * 16;
                uint32_t a[2][4], bf[4][2];
#pragma unroll
                for (int mt = 0; mt < 2; mt++)
                    LDSM_X4(a[mt][0], a[mt][1], a[mt][2], a[mt][3],
                            Ab_ + ((rm + mt * 16 + arow) * APITCH + k0 + akol) * 2);
#pragma unroll
                for (int nt = 0; nt < 4; nt++)
                    LDSM_X2(bf[nt][0], bf[nt][1],
                            Bb_ + ((cn + nt * 8 + brow) * APITCH + k0 + bkol) * 2);
#pragma unroll
                for (int mt = 0; mt < 2; mt++)
#pragma unroll
                    for (int nt = 0; nt < 4; nt++)
                        MMA16816(acc[mt][nt], a[mt], bf[nt]);
            }
        }

        // residual + bias; LN partials
#pragma unroll
        for (int mt = 0; mt < 2; mt++) {
            int rlo = rm + mt * 16 + qrow;
            int rhi = rlo + 8;
            float sLo = 0.0f, qLo = 0.0f, sHi = 0.0f, qHi = 0.0f;
#pragma unroll
            for (int nt = 0; nt < 4; nt++) {
                int col = cn + nt * 8 + qcol;
                float bx = __ldg(b2 + col), by = __ldg(b2 + col + 1);
                float2 zlo = *(const float2*)(ztLN_g + (size_t)(rowBase + rlo) * 128 + col);
                float2 zhi = *(const float2*)(ztLN_g + (size_t)(rowBase + rhi) * 128 + col);
                acc[mt][nt][0] += zlo.x + bx;
                acc[mt][nt][1] += zlo.y + by;
                acc[mt][nt][2] += zhi.x + bx;
                acc[mt][nt][3] += zhi.y + by;
                sLo += acc[mt][nt][0] + acc[mt][nt][1];
                qLo += acc[mt][nt][0] * acc[mt][nt][0] + acc[mt][nt][1] * acc[mt][nt][1];
                sHi += acc[mt][nt][2] + acc[mt][nt][3];
                qHi += acc[mt][nt][2] * acc[mt][nt][2] + acc[mt][nt][3] * acc[mt][nt][3];
            }
#pragma unroll
            for (int sh = 1; sh < 4; sh <<= 1) {
                sLo += __shfl_xor_sync(0xffffffffu, sLo, sh);
                qLo += __shfl_xor_sync(0xffffffffu, qLo, sh);
                sHi += __shfl_xor_sync(0xffffffffu, sHi, sh);
                qHi += __shfl_xor_sync(0xffffffffu, qHi, sh);
            }
            if ((lane & 3) == 0) {
                redS[rlo * 4 + warp_n] = sLo;
                redQ[rlo * 4 + warp_n] = qLo;
                redS[rhi * 4 + warp_n] = sHi;
                redQ[rhi * 4 + warp_n] = qHi;
            }
        }
        __syncthreads();   // red ready; A reads done -> stg may overwrite A

        // finalize LN per row; write transposed staging stg[col][row]
#pragma unroll
        for (int mt = 0; mt < 2; mt++) {
            int rlo = rm + mt * 16 + qrow;
            int rhi = rlo + 8;
            float sLo = redS[rlo * 4 + 0] + redS[rlo * 4 + 1] + redS[rlo * 4 + 2] + redS[rlo * 4 + 3];
            float qLo = redQ[rlo * 4 + 0] + redQ[rlo * 4 + 1] + redQ[rlo * 4 + 2] + redQ[rlo * 4 + 3];
            float sHi = redS[rhi * 4 + 0] + redS[rhi * 4 + 1] + redS[rhi * 4 + 2] + redS[rhi * 4 + 3];
            float qHi = redQ[rhi * 4 + 0] + redQ[rhi * 4 + 1] + redQ[rhi * 4 + 2] + redQ[rhi * 4 + 3];
            float mLo = sLo * (1.0f / 128.0f);
            float rLo = rsqrtf(qLo * (1.0f / 128.0f) - mLo * mLo + 1e-5f);
            float mHi = sHi * (1.0f / 128.0f);
            float rHi = rsqrtf(qHi * (1.0f / 128.0f) - mHi * mHi + 1e-5f);
#pragma unroll
            for (int nt = 0; nt < 4; nt++) {
                int col = cn + nt * 8 + qcol;
                float lwx = __ldg(ln2w + col), lwy = __ldg(ln2w + col + 1);
                float lbx = __ldg(ln2b + col), lby = __ldg(ln2b + col + 1);
                stg[(col + 0) * STGP + rlo] = (acc[mt][nt][0] - mLo) * rLo * lwx + lbx;
                stg[(col + 1) * STGP + rlo] = (acc[mt][nt][1] - mLo) * rLo * lwy + lby;
                stg[(col + 0) * STGP + rhi] = (acc[mt][nt][2] - mHi) * rHi * lwx + lbx;
                stg[(col + 1) * STGP + rhi] = (acc[mt][nt][3] - mHi) * rHi * lwy + lby;
            }
        }
        __syncthreads();

        int b = rowBase >> 14;
        int prowBase = rowBase & (Pp - 1);
        for (int idx = tid; idx < 4096; idx += 512) {
            int c = idx >> 5;
            int j = (idx & 31) * 4;
            float4 v = *(const float4*)(stg + c * STGP + j);
            *(float4*)(out + ((size_t)(b * 128 + c)) * Pp + prowBase + j) = v;
        }
        __syncthreads();   // stores done before next tile's A fill
    }
}

// ---------------------------------------------------------------
extern "C" void kernel_launch(void* const* d_in, const int* in_sizes, int n_in,
                              void* d_out, int out_size) {
    const float* query = (const float*)d_in[0];
    const float* ref   = (const float*)d_in[1];
    const float* homo  = (const float*)d_in[2];
    const float* ln1w  = (const float*)d_in[3];
    const float* ln1b  = (const float*)d_in[4];
    const float* ln2w  = (const float*)d_in[5];
    const float* ln2b  = (const float*)d_in[6];
    const float* w1    = (const float*)d_in[7];
    const float* b1    = (const float*)d_in[8];
    const float* w2    = (const float*)d_in[9];
    const float* b2    = (const float*)d_in[10];
    float* out = (float*)d_out;

    cudaFuncSetAttribute(gemm1_mma, cudaFuncAttributeMaxDynamicSharedMemorySize, G1_SMEM);
    cudaFuncSetAttribute(gemm2_mma, cudaFuncAttributeMaxDynamicSharedMemorySize, G2_SMEM);

    prep_all_kernel<<<dim3(Pp / 32, 1, 29), 256>>>(ref, query, w1, w2);
    attn_kernel<<<Mm / 16, 256>>>(homo, ln1w, ln1b);
    gemm1_mma<<<NSM, 512, G1_SMEM>>>(b1);
    gemm2_mma<<<NSM, 512, G2_SMEM>>>(b2, ln2w, ln2b, out);
}

// round 14
// speedup vs baseline: 1.3926x; 1.3926x over previous
#include <cuda_runtime.h>
#include <cuda_fp16.h>
#include <math.h>
#include <stdint.h>

#define Pp 16384
#define Dd 128
#define Bb 4
#define Nn 6
#define Mm 65536   // B*P rows

// ---- scratch (static device globals; no allocation allowed) ----
__device__ __half  refTh_g[(size_t)Bb * Nn * Pp * Dd]; // (bn, p, d) fp16
__device__ float   qT_g[(size_t)Bb * Pp * Dd];         // (bp, d) fp32
__device__ float   ztLN_g[(size_t)Bb * Pp * Dd];       // (bp, d) fp32 (residual)
__device__ __half  ztLNh_g[(size_t)Mm * Dd];           // fp16 copy for GEMM1
__device__ __half  hbufh_g[(size_t)Mm * 256];          // gelu output fp16
__device__ __half  W1h_g[256 * 128];                   // [n][k] fp16
__device__ __half  W2h_g[128 * 256];                   // [n][k] fp16

// ---------------------------------------------------------------
// helpers
// ---------------------------------------------------------------
__device__ __forceinline__ float wsum16(float v) {
#pragma unroll
    for (int s = 1; s < 16; s <<= 1) v += __shfl_xor_sync(0xffffffffu, v, s);
    return v;
}
__device__ __forceinline__ float gelu_exact(float x) {
    return 0.5f * x * (1.0f + erff(x * 0.70710678118654752440f));
}
__device__ __forceinline__ void h8_to_f8(uint4 u, float* f) {
    float2 t;
    t = __half22float2(*reinterpret_cast<__half2*>(&u.x)); f[0] = t.x; f[1] = t.y;
    t = __half22float2(*reinterpret_cast<__half2*>(&u.y)); f[2] = t.x; f[3] = t.y;
    t = __half22float2(*reinterpret_cast<__half2*>(&u.z)); f[4] = t.x; f[5] = t.y;
    t = __half22float2(*reinterpret_cast<__half2*>(&u.w)); f[6] = t.x; f[7] = t.y;
}
__device__ __forceinline__ uint32_t smem_u32(const void* p) {
    uint32_t a;
    asm("{ .reg .u64 t; cvta.to.shared.u64 t, %1; cvt.u32.u64 %0, t; }" : "=r"(a) : "l"(p));
    return a;
}

#define LDSM_X4(r0, r1, r2, r3, a) \
    asm volatile("ldmatrix.sync.aligned.m8n8.x4.shared.b16 {%0,%1,%2,%3}, [%4];" \
                 : "=r"(r0), "=r"(r1), "=r"(r2), "=r"(r3) : "r"(a))
#define LDSM_X2(r0, r1, a) \
    asm volatile("ldmatrix.sync.aligned.m8n8.x2.shared.b16 {%0,%1}, [%2];" \
                 : "=r"(r0), "=r"(r1) : "r"(a))
#define MMA16816(d, a, b) \
    asm volatile("mma.sync.aligned.m16n8k16.row.col.f32.f16.f16.f32 " \
                 "{%0,%1,%2,%3}, {%4,%5,%6,%7}, {%8,%9}, {%0,%1,%2,%3};" \
                 : "+f"((d)[0]), "+f"((d)[1]), "+f"((d)[2]), "+f"((d)[3]) \
                 : "r"((a)[0]), "r"((a)[1]), "r"((a)[2]), "r"((a)[3]), \
                   "r"((b)[0]), "r"((b)[1]))

#define APITCH 136   // halves per smem row (128 + 8 pad -> conflict-free ldmatrix)

// ---------------------------------------------------------------
// Merged prep: z<24 -> ref transpose to fp16; z in [24,28) -> q transpose
// to fp32; z==28 -> weight conversion.
// ---------------------------------------------------------------
__global__ void __launch_bounds__(256) prep_all_kernel(const float* __restrict__ ref,
                                                       const float* __restrict__ query,
                                                       const float* __restrict__ W1,
                                                       const float* __restrict__ W2) {
    int z = blockIdx.z;
    if (z == 28) {
        int idx = blockIdx.x * 256 + threadIdx.x;
        if (idx < 32768) {
            int n = idx >> 7, k = idx & 127;
            W1h_g[idx] = __float2half(W1[(size_t)k * 256 + n]);
        } else if (idx < 65536) {
            int j = idx - 32768;
            int n = j >> 8, k = j & 255;
            W2h_g[j] = __float2half(W2[(size_t)k * 128 + n]);
        }
        return;
    }

    __shared__ float tile[32][129];
    int p0 = blockIdx.x * 32;
    int lane = threadIdx.x & 31;
    int ty = threadIdx.x >> 5;

    if (z < 24) {
        const float* src = ref + (size_t)z * Dd * Pp;
        __half* dst = refTh_g + (size_t)z * Pp * Dd;
#pragma unroll
        for (int it = 0; it < 16; it++) {
            int d = it * 8 + ty;
            tile[lane][d] = src[(size_t)d * Pp + p0 + lane];
        }
        __syncthreads();
        int pi = threadIdx.x & 63;
        int ppb = threadIdx.x >> 6;
#pragma unroll
        for (int it = 0; it < 8; it++) {
            int pp = it * 4 + ppb;
            float2 f = make_float2(tile[pp][2 * pi], tile[pp][2 * pi + 1]);
            *(__half2*)(dst + (size_t)(p0 + pp) * Dd + 2 * pi) = __float22half2_rn(f);
        }
    } else {
        int mat = z - 24;
        const float* src = query + (size_t)mat * Dd * Pp;
        float* dst = qT_g + (size_t)mat * Dd * Pp;
#pragma unroll
        for (int it = 0; it < 16; it++) {
            int d = it * 8 + ty;
            tile[lane][d] = src[(size_t)d * Pp + p0 + lane];
        }
        __syncthreads();
#pragma unroll
        for (int it = 0; it < 16; it++) {
            int idx = it * 256 + threadIdx.x;
            int pp = idx >> 7, d = idx & 127;
            dst[(size_t)(p0 + pp) * Dd + d] = tile[pp][d];
        }
    }
}

// ---------------------------------------------------------------
// Attention: 2 pixels/warp, 16 lanes/pixel, 8 ch/lane, 4 CTAs/SM.
// (unchanged from R9/R11-best)
// ---------------------------------------------------------------
__global__ void __launch_bounds__(256, 4) attn_kernel(const float* __restrict__ homo,
                                                      const float* __restrict__ ln1w,
                                                      const float* __restrict__ ln1b) {
    int lane = threadIdx.x & 31;
    int warp = threadIdx.x >> 5;
    int sub = lane >> 4;
    int sl = lane & 15;
    int gp = blockIdx.x * 16 + warp * 2 + sub;
    int b = gp >> 14;
    int p = gp & (Pp - 1);

    float us[6], vs[6];
#pragma unroll
    for (int n = 0; n < 6; n++) {
        int bn = b * Nn + n;
        us[n] = homo[(size_t)(bn * 2 + 0) * Pp + p] * 128.0f;
        vs[n] = homo[(size_t)(bn * 2 + 1) * Pp + p] * 128.0f;
    }

    float q[8];
    {
        float4 q0 = *(const float4*)(qT_g + (size_t)gp * Dd + sl * 8);
        float4 q1 = *(const float4*)(qT_g + (size_t)gp * Dd + sl * 8 + 4);
        q[0] = q0.x; q[1] = q0.y; q[2] = q0.z; q[3] = q0.w;
        q[4] = q1.x; q[5] = q1.y; q[6] = q1.z; q[7] = q1.w;
    }
    float qn2 = 0.0f;
#pragma unroll
    for (int k = 0; k < 8; k++) qn2 += q[k] * q[k];
    qn2 = wsum16(qn2);
    float qden = fmaxf(sqrtf(qn2), 1e-12f);

    __half2 vh[6][4];
    float dots[6];

#pragma unroll
    for (int n = 0; n < 6; n++) {
        int bn = b * Nn + n;
        float u = us[n], v = vs[n];
        float wx = u - floorf(u), wy = v - floorf(v);
        int ix0 = min(max(__float2int_rd(u), 0), 127);
        int ix1 = min(max(__float2int_rd(u) + 1, 0), 127);
        int iy0 = min(max(__float2int_rd(v), 0), 127);
        int iy1 = min(max(__float2int_rd(v) + 1, 0), 127);
        bool valid = (u >= 0.0f) && (u <= 127.0f) && (v >= 0.0f) && (v <= 127.0f);

        const __half* base = refTh_g + (size_t)bn * Pp * Dd + sl * 8;
        uint4 r00 = *(const uint4*)(base + ((iy0 << 7) + ix0) * Dd);
        uint4 r10 = *(const uint4*)(base + ((iy0 << 7) + ix1) * Dd);
        uint4 r01 = *(const uint4*)(base + ((iy1 << 7) + ix0) * Dd);
        uint4 r11 = *(const uint4*)(base + ((iy1 << 7) + ix1) * Dd);

        float c00[8], c10[8], c01[8], c11[8];
        h8_to_f8(r00, c00); h8_to_f8(r10, c10);
        h8_to_f8(r01, c01); h8_to_f8(r11, c11);

        float w00 = (1.0f - wx) * (1.0f - wy);
        float w10 = wx * (1.0f - wy);
        float w01 = (1.0f - wx) * wy;
        float w11 = wx * wy;

        float v2 = 0.0f, s = 0.0f;
#pragma unroll
        for (int k = 0; k < 8; k += 2) {
            float val0 = w00 * c00[k] + w10 * c10[k] + w01 * c01[k] + w11 * c11[k];
            float val1 = w00 * c00[k + 1] + w10 * c10[k + 1] + w01 * c01[k + 1] + w11 * c11[k + 1];
            vh[n][k >> 1] = __floats2half2_rn(val0, val1);
            v2 += val0 * val0 + val1 * val1;
            s += q[k] * val0 + q[k + 1] * val1;
        }
        v2 = wsum16(v2);
        s = wsum16(s);
        float vden = fmaxf(sqrtf(v2), 1e-12f);
        dots[n] = valid ? __fdividef(s, qden * vden) : 0.0f;
    }

    float m = dots[0];
#pragma unroll
    for (int n = 1; n < 6; n++) m = fmaxf(m, dots[n]);
    float e[6], esum = 0.0f;
#pragma unroll
    for (int n = 0; n < 6; n++) { e[n] = __expf(dots[n] - m); esum += e[n]; }
    float inv = __fdividef(1.0f, esum);

#pragma unroll
    for (int k2 = 0; k2 < 4; k2++) {
        float zx = 0.0f, zy = 0.0f;
#pragma unroll
        for (int n = 0; n < 6; n++) {
            float2 vv = __half22float2(vh[n][k2]);
            zx += e[n] * vv.x;
            zy += e[n] * vv.y;
        }
        q[2 * k2] += zx * inv;
        q[2 * k2 + 1] += zy * inv;
    }

    float ssum = 0.0f;
#pragma unroll
    for (int k = 0; k < 8; k++) ssum += q[k];
    float mean = wsum16(ssum) * (1.0f / 128.0f);
    float dv = 0.0f;
#pragma unroll
    for (int k = 0; k < 8; k++) { float dd = q[k] - mean; dv += dd * dd; }
    float rstd = rsqrtf(wsum16(dv) * (1.0f / 128.0f) + 1e-5f);

    float o[8];
    {
        float4 lw0 = *(const float4*)(ln1w + sl * 8);
        float4 lw1 = *(const float4*)(ln1w + sl * 8 + 4);
        float4 lb0 = *(const float4*)(ln1b + sl * 8);
        float4 lb1 = *(const float4*)(ln1b + sl * 8 + 4);
        o[0] = (q[0] - mean) * rstd * lw0.x + lb0.x;
        o[1] = (q[1] - mean) * rstd * lw0.y + lb0.y;
        o[2] = (q[2] - mean) * rstd * lw0.z + lb0.z;
        o[3] = (q[3] - mean) * rstd * lw0.w + lb0.w;
        o[4] = (q[4] - mean) * rstd * lw1.x + lb1.x;
        o[5] = (q[5] - mean) * rstd * lw1.y + lb1.y;
        o[6] = (q[6] - mean) * rstd * lw1.z + lb1.z;
        o[7] = (q[7] - mean) * rstd * lw1.w + lb1.w;
    }
    float* dstf = ztLN_g + (size_t)gp * Dd + sl * 8;
    *(float4*)dstf = make_float4(o[0], o[1], o[2], o[3]);
    *(float4*)(dstf + 4) = make_float4(o[4], o[5], o[6], o[7]);

    __half2 h[4];
    h[0] = __floats2half2_rn(o[0], o[1]);
    h[1] = __floats2half2_rn(o[2], o[3]);
    h[2] = __floats2half2_rn(o[4], o[5]);
    h[3] = __floats2half2_rn(o[6], o[7]);
    *(float4*)(ztLNh_g + (size_t)gp * Dd + sl * 8) = *(float4*)h;
}

// ---------------------------------------------------------------
// GEMM1 (mma.sync, BM=64, N-split grid.y=2): H = gelu(ztLNh @ W1 + b1).
// smem 52.2KB, ~70 regs -> 3-4 CTAs/SM.
// ---------------------------------------------------------------
#define G1_SMEM (64 * APITCH * 2 + 128 * APITCH * 2)   // 52224
__global__ void __launch_bounds__(256) gemm1_mma(const float* __restrict__ b1) {
    extern __shared__ __half sm1[];
    __half* Ah = sm1;                     // 64 x APITCH
    __half* Bh = sm1 + 64 * APITCH;       // 128 x APITCH (N half)
    uint32_t Abase = smem_u32(Ah), Bbase = smem_u32(Bh);

    int tid = threadIdx.x;
    int warp = tid >> 5, lane = tid & 31;
    int rowBase = blockIdx.x * 64;
    int colBase = blockIdx.y * 128;

    for (int idx = tid; idx < 1024; idx += 256) {
        int r = idx >> 4, kg = (idx & 15) << 3;
        *(float4*)(Ah + r * APITCH + kg) =
            *(const float4*)(ztLNh_g + (size_t)(rowBase + r) * 128 + kg);
    }
    for (int idx = tid; idx < 2048; idx += 256) {
        int r = idx >> 4, kg = (idx & 15) << 3;
        *(float4*)(Bh + r * APITCH + kg) =
            *(const float4*)(W1h_g + (size_t)(colBase + r) * 128 + kg);
    }
    __syncthreads();

    int warp_m = warp & 1, warp_n = warp >> 1;
    int rm = warp_m * 32, cn = warp_n * 32;
    int arow = (lane & 7) + ((lane >> 3) & 1) * 8;
    int akol = (lane >> 4) * 8;
    int brow = lane & 7;
    int bkol = ((lane >> 3) & 1) * 8;
    int qrow = lane >> 2, qcol = (lane & 3) * 2;

    float acc[2][4][4] = {};
#pragma unroll
    for (int ks = 0; ks < 8; ks++) {
        int k0 = ks * 16;
        uint32_t a[2][4], bf[4][2];
#pragma unroll
        for (int mt = 0; mt < 2; mt++)
            LDSM_X4(a[mt][0], a[mt][1], a[mt][2], a[mt][3],
                    Abase + ((rm + mt * 16 + arow) * APITCH + k0 + akol) * 2);
#pragma unroll
        for (int nt = 0; nt < 4; nt++)
            LDSM_X2(bf[nt][0], bf[nt][1],
                    Bbase + ((cn + nt * 8 + brow) * APITCH + k0 + bkol) * 2);
#pragma unroll
        for (int mt = 0; mt < 2; mt++)
#pragma unroll
            for (int nt = 0; nt < 4; nt++)
                MMA16816(acc[mt][nt], a[mt], bf[nt]);
    }

#pragma unroll
    for (int nt = 0; nt < 4; nt++) {
        int col = colBase + cn + nt * 8 + qcol;
        float bx = __ldg(b1 + col), by = __ldg(b1 + col + 1);
#pragma unroll
        for (int mt = 0; mt < 2; mt++) {
            int row = rowBase + rm + mt * 16 + qrow;
            __half2 h0 = __floats2half2_rn(gelu_exact(acc[mt][nt][0] + bx),
                                           gelu_exact(acc[mt][nt][1] + by));
            __half2 h1 = __floats2half2_rn(gelu_exact(acc[mt][nt][2] + bx),
                                           gelu_exact(acc[mt][nt][3] + by));
            *(__half2*)(hbufh_g + (size_t)row * 256 + col) = h0;
            *(__half2*)(hbufh_g + (size_t)(row + 8) * 256 + col) = h1;
        }
    }
}

// ---------------------------------------------------------------
// GEMM2 (mma.sync, BM=64, B streamed): zt2 = ztLN + hbufh @ W2 + b2;
// LN2; transposed store. B chunks pass through ONE 34.8KB buffer.
// smem 71.7KB, ~80 regs -> 3 CTAs/SM.
// ---------------------------------------------------------------
#define G2A0_OFF  0
#define G2A1_OFF  (64 * APITCH)
#define G2B_OFF   (128 * APITCH)
#define G2RED_OFF (256 * APITCH)
#define G2_SMEM   (256 * APITCH * 2 + 2048)     // 71680 bytes
#define STGP 68   // float stride for staging [128][STGP] (reuses A0+A1)
__global__ void __launch_bounds__(256) gemm2_mma(const float* __restrict__ b2,
                                                 const float* __restrict__ ln2w,
                                                 const float* __restrict__ ln2b,
                                                 float* __restrict__ out) {
    extern __shared__ __half sm2[];
    __half* A0 = sm2 + G2A0_OFF;
    __half* A1 = sm2 + G2A1_OFF;
    __half* Bh = sm2 + G2B_OFF;
    float* redS = (float*)(sm2 + G2RED_OFF);     // [64][4]
    float* redQ = redS + 256;                    // [64][4]
    float* stg  = (float*)sm2;                   // [128][STGP] reuse A0+A1 (34.8KB)
    uint32_t A0b = smem_u32(A0), A1b = smem_u32(A1);
    uint32_t Bbase = smem_u32(Bh);

    int tid = threadIdx.x;
    int warp = tid >> 5, lane = tid & 31;
    int rowBase = blockIdx.x * 64;

    // A both chunks (64x256) + B chunk0
    for (int idx = tid; idx < 1024; idx += 256) {
        int r = idx >> 4, kg = (idx & 15) << 3;
        *(float4*)(A0 + r * APITCH + kg) =
            *(const float4*)(hbufh_g + (size_t)(rowBase + r) * 256 + kg);
        *(float4*)(A1 + r * APITCH + kg) =
            *(const float4*)(hbufh_g + (size_t)(rowBase + r) * 256 + 128 + kg);
    }
    for (int idx = tid; idx < 2048; idx += 256) {
        int r = idx >> 4, kg = (idx & 15) << 3;
        *(float4*)(Bh + r * APITCH + kg) =
            *(const float4*)(W2h_g + (size_t)r * 256 + kg);
    }
    __syncthreads();

    int warp_m = warp & 1, warp_n = warp >> 1;
    int rm = warp_m * 32, cn = warp_n * 32;
    int arow = (lane & 7) + ((lane >> 3) & 1) * 8;
    int akol = (lane >> 4) * 8;
    int brow = lane & 7;
    int bkol = ((lane >> 3) & 1) * 8;

    float acc[2][4][4] = {};
#pragma unroll
    for (int kc = 0; kc < 2; kc++) {
        uint32_t Ab_ = kc ? A1b : A0b;
#pragma unroll
        for (int ks = 0; ks < 8; ks++) {
            int k0 = ks * 16;
            uint32_t a[2][4], bf[4][2];
#pragma unroll
            for (int mt = 0; mt < 2; mt++)
                LDSM_X4(a[mt][0], a[mt][1], a[mt][2], a[mt][3],
                        Ab_ + ((rm + mt * 16 + arow) * APITCH + k0 + akol) * 2);
#pragma unroll
            for (int nt = 0; nt < 4; nt++)
                LDSM_X2(bf[nt][0], bf[nt][1],
                        Bbase + ((cn + nt * 8 + brow) * APITCH + k0 + bkol) * 2);
#pragma unroll
            for (int mt = 0; mt < 2; mt++)
#pragma unroll
                for (int nt = 0; nt < 4; nt++)
                    MMA16816(acc[mt][nt], a[mt], bf[nt]);
        }
        if (kc == 0) {
            __syncthreads();   // B chunk0 reads done
            for (int idx = tid; idx < 2048; idx += 256) {
                int r = idx >> 4, kg = (idx & 15) << 3;
                *(float4*)(Bh + r * APITCH + kg) =
                    *(const float4*)(W2h_g + (size_t)r * 256 + 128 + kg);
            }
            __syncthreads();
        }
    }

    int qrow = lane >> 2, qcol = (lane & 3) * 2;

    // residual + bias; LN partials
#pragma unroll
    for (int mt = 0; mt < 2; mt++) {
        int rlo = rm + mt * 16 + qrow;
        int rhi = rlo + 8;
        float sLo = 0.0f, qLo = 0.0f, sHi = 0.0f, qHi = 0.0f;
#pragma unroll
        for (int nt = 0; nt < 4; nt++) {
            int col = cn + nt * 8 + qcol;
            float bx = __ldg(b2 + col), by = __ldg(b2 + col + 1);
            float2 zlo = *(const float2*)(ztLN_g + (size_t)(rowBase + rlo) * 128 + col);
            float2 zhi = *(const float2*)(ztLN_g + (size_t)(rowBase + rhi) * 128 + col);
            acc[mt][nt][0] += zlo.x + bx;
            acc[mt][nt][1] += zlo.y + by;
            acc[mt][nt][2] += zhi.x + bx;
            acc[mt][nt][3] += zhi.y + by;
            sLo += acc[mt][nt][0] + acc[mt][nt][1];
            qLo += acc[mt][nt][0] * acc[mt][nt][0] + acc[mt][nt][1] * acc[mt][nt][1];
            sHi += acc[mt][nt][2] + acc[mt][nt][3];
            qHi += acc[mt][nt][2] * acc[mt][nt][2] + acc[mt][nt][3] * acc[mt][nt][3];
        }
#pragma unroll
        for (int sh = 1; sh < 4; sh <<= 1) {
            sLo += __shfl_xor_sync(0xffffffffu, sLo, sh);
            qLo += __shfl_xor_sync(0xffffffffu, qLo, sh);
            sHi += __shfl_xor_sync(0xffffffffu, sHi, sh);
            qHi += __shfl_xor_sync(0xffffffffu, qHi, sh);
        }
        if ((lane & 3) == 0) {
            redS[rlo * 4 + warp_n] = sLo;
            redQ[rlo * 4 + warp_n] = qLo;
            redS[rhi * 4 + warp_n] = sHi;
            redQ[rhi * 4 + warp_n] = qHi;
        }
    }
    __syncthreads();   // red ready; A/B LDSM reads done -> stg may overwrite A

    // finalize LN per row; transposed staging stg[col][row]
#pragma unroll
    for (int mt = 0; mt < 2; mt++) {
        int rlo = rm + mt * 16 + qrow;
        int rhi = rlo + 8;
        float sLo = redS[rlo * 4 + 0] + redS[rlo * 4 + 1] + redS[rlo * 4 + 2] + redS[rlo * 4 + 3];
        float qLo = redQ[rlo * 4 + 0] + redQ[rlo * 4 + 1] + redQ[rlo * 4 + 2] + redQ[rlo * 4 + 3];
        float sHi = redS[rhi * 4 + 0] + redS[rhi * 4 + 1] + redS[rhi * 4 + 2] + redS[rhi * 4 + 3];
        float qHi = redQ[rhi * 4 + 0] + redQ[rhi * 4 + 1] + redQ[rhi * 4 + 2] + redQ[rhi * 4 + 3];
        float mLo = sLo * (1.0f / 128.0f);
        float rLo = rsqrtf(qLo * (1.0f / 128.0f) - mLo * mLo + 1e-5f);
        float mHi = sHi * (1.0f / 128.0f);
        float rHi = rsqrtf(qHi * (1.0f / 128.0f) - mHi * mHi + 1e-5f);
#pragma unroll
        for (int nt = 0; nt < 4; nt++) {
            int col = cn + nt * 8 + qcol;
            float lwx = __ldg(ln2w + col), lwy = __ldg(ln2w + col + 1);
            float lbx = __ldg(ln2b + col), lby = __ldg(ln2b + col + 1);
            stg[(col + 0) * STGP + rlo] = (acc[mt][nt][0] - mLo) * rLo * lwx + lbx;
            stg[(col + 1) * STGP + rlo] = (acc[mt][nt][1] - mLo) * rLo * lwy + lby;
            stg[(col + 0) * STGP + rhi] = (acc[mt][nt][2] - mHi) * rHi * lwx + lbx;
            stg[(col + 1) * STGP + rhi] = (acc[mt][nt][3] - mHi) * rHi * lwy + lby;
        }
    }
    __syncthreads();

    int b = rowBase >> 14;
    int prowBase = rowBase & (Pp - 1);
    for (int idx = tid; idx < 2048; idx += 256) {
        int c = idx >> 4;
        int j = (idx & 15) * 4;
        float4 v = *(const float4*)(stg + c * STGP + j);
        *(float4*)(out + ((size_t)(b * 128 + c)) * Pp + prowBase + j) = v;
    }
}

// ---------------------------------------------------------------
extern "C" void kernel_launch(void* const* d_in, const int* in_sizes, int n_in,
                              void* d_out, int out_size) {
    const float* query = (const float*)d_in[0];
    const float* ref   = (const float*)d_in[1];
    const float* homo  = (const float*)d_in[2];
    const float* ln1w  = (const float*)d_in[3];
    const float* ln1b  = (const float*)d_in[4];
    const float* ln2w  = (const float*)d_in[5];
    const float* ln2b  = (const float*)d_in[6];
    const float* w1    = (const float*)d_in[7];
    const float* b1    = (const float*)d_in[8];
    const float* w2    = (const float*)d_in[9];
    const float* b2    = (const float*)d_in[10];
    float* out = (float*)d_out;

    cudaFuncSetAttribute(gemm1_mma, cudaFuncAttributeMaxDynamicSharedMemorySize, G1_SMEM);
    cudaFuncSetAttribute(gemm2_mma, cudaFuncAttributeMaxDynamicSharedMemorySize, G2_SMEM);

    prep_all_kernel<<<dim3(Pp / 32, 1, 29), 256>>>(ref, query, w1, w2);
    attn_kernel<<<Mm / 16, 256>>>(homo, ln1w, ln1b);
    gemm1_mma<<<dim3(Mm / 64, 2), 256, G1_SMEM>>>(b1);
    gemm2_mma<<<Mm / 64, 256, G2_SMEM>>>(b2, ln2w, ln2b, out);
}

// round 15
// speedup vs baseline: 1.4474x; 1.0393x over previous
#include <cuda_runtime.h>
#include <cuda_fp16.h>
#include <math.h>
#include <stdint.h>

#define Pp 16384
#define Dd 128
#define Bb 4
#define Nn 6
#define Mm 65536   // B*P rows

// ---- scratch (static device globals; no allocation allowed) ----
__device__ __half  refTh_g[(size_t)Bb * Nn * Pp * Dd]; // (bn, p, d) fp16
__device__ float   qT_g[(size_t)Bb * Pp * Dd];         // (bp, d) fp32
__device__ float   ztLN_g[(size_t)Bb * Pp * Dd];       // (bp, d) fp32 (residual)
__device__ __half  ztLNh_g[(size_t)Mm * Dd];           // fp16 copy for MLP
__device__ __half  W1h_g[256 * 128];                   // [n][k] fp16
__device__ __half  W2h_g[128 * 256];                   // [n][k] fp16

// ---------------------------------------------------------------
// helpers
// ---------------------------------------------------------------
__device__ __forceinline__ float wsum16(float v) {
#pragma unroll
    for (int s = 1; s < 16; s <<= 1) v += __shfl_xor_sync(0xffffffffu, v, s);
    return v;
}
__device__ __forceinline__ float gelu_exact(float x) {
    return 0.5f * x * (1.0f + erff(x * 0.70710678118654752440f));
}
__device__ __forceinline__ void h8_to_f8(uint4 u, float* f) {
    float2 t;
    t = __half22float2(*reinterpret_cast<__half2*>(&u.x)); f[0] = t.x; f[1] = t.y;
    t = __half22float2(*reinterpret_cast<__half2*>(&u.y)); f[2] = t.x; f[3] = t.y;
    t = __half22float2(*reinterpret_cast<__half2*>(&u.z)); f[4] = t.x; f[5] = t.y;
    t = __half22float2(*reinterpret_cast<__half2*>(&u.w)); f[6] = t.x; f[7] = t.y;
}
__device__ __forceinline__ uint32_t smem_u32(const void* p) {
    uint32_t a;
    asm("{ .reg .u64 t; cvta.to.shared.u64 t, %1; cvt.u32.u64 %0, t; }" : "=r"(a) : "l"(p));
    return a;
}

#define LDSM_X4(r0, r1, r2, r3, a) \
    asm volatile("ldmatrix.sync.aligned.m8n8.x4.shared.b16 {%0,%1,%2,%3}, [%4];" \
                 : "=r"(r0), "=r"(r1), "=r"(r2), "=r"(r3) : "r"(a))
#define LDSM_X2(r0, r1, a) \
    asm volatile("ldmatrix.sync.aligned.m8n8.x2.shared.b16 {%0,%1}, [%2];" \
                 : "=r"(r0), "=r"(r1) : "r"(a))
#define MMA16816(d, a, b) \
    asm volatile("mma.sync.aligned.m16n8k16.row.col.f32.f16.f16.f32 " \
                 "{%0,%1,%2,%3}, {%4,%5,%6,%7}, {%8,%9}, {%0,%1,%2,%3};" \
                 : "+f"((d)[0]), "+f"((d)[1]), "+f"((d)[2]), "+f"((d)[3]) \
                 : "r"((a)[0]), "r"((a)[1]), "r"((a)[2]), "r"((a)[3]), \
                   "r"((b)[0]), "r"((b)[1]))

#define APITCH 136   // halves per smem row (128 + 8 pad -> conflict-free ldmatrix)

// ---------------------------------------------------------------
// Merged prep: z<24 -> ref transpose to fp16; z in [24,28) -> q transpose
// to fp32; z==28 -> weight conversion.
// ---------------------------------------------------------------
__global__ void __launch_bounds__(256) prep_all_kernel(const float* __restrict__ ref,
                                                       const float* __restrict__ query,
                                                       const float* __restrict__ W1,
                                                       const float* __restrict__ W2) {
    int z = blockIdx.z;
    if (z == 28) {
        int idx = blockIdx.x * 256 + threadIdx.x;
        if (idx < 32768) {
            int n = idx >> 7, k = idx & 127;
            W1h_g[idx] = __float2half(W1[(size_t)k * 256 + n]);
        } else if (idx < 65536) {
            int j = idx - 32768;
            int n = j >> 8, k = j & 255;
            W2h_g[j] = __float2half(W2[(size_t)k * 128 + n]);
        }
        return;
    }

    __shared__ float tile[32][129];
    int p0 = blockIdx.x * 32;
    int lane = threadIdx.x & 31;
    int ty = threadIdx.x >> 5;

    if (z < 24) {
        const float* src = ref + (size_t)z * Dd * Pp;
        __half* dst = refTh_g + (size_t)z * Pp * Dd;
#pragma unroll
        for (int it = 0; it < 16; it++) {
            int d = it * 8 + ty;
            tile[lane][d] = src[(size_t)d * Pp + p0 + lane];
        }
        __syncthreads();
        int pi = threadIdx.x & 63;
        int ppb = threadIdx.x >> 6;
#pragma unroll
        for (int it = 0; it < 8; it++) {
            int pp = it * 4 + ppb;
            float2 f = make_float2(tile[pp][2 * pi], tile[pp][2 * pi + 1]);
            *(__half2*)(dst + (size_t)(p0 + pp) * Dd + 2 * pi) = __float22half2_rn(f);
        }
    } else {
        int mat = z - 24;
        const float* src = query + (size_t)mat * Dd * Pp;
        float* dst = qT_g + (size_t)mat * Dd * Pp;
#pragma unroll
        for (int it = 0; it < 16; it++) {
            int d = it * 8 + ty;
            tile[lane][d] = src[(size_t)d * Pp + p0 + lane];
        }
        __syncthreads();
#pragma unroll
        for (int it = 0; it < 16; it++) {
            int idx = it * 256 + threadIdx.x;
            int pp = idx >> 7, d = idx & 127;
            dst[(size_t)(p0 + pp) * Dd + d] = tile[pp][d];
        }
    }
}

// ---------------------------------------------------------------
// Attention: 2 pixels/warp, 16 lanes/pixel, 8 ch/lane, 4 CTAs/SM.
// (unchanged from R14-best)
// ---------------------------------------------------------------
__global__ void __launch_bounds__(256, 4) attn_kernel(const float* __restrict__ homo,
                                                      const float* __restrict__ ln1w,
                                                      const float* __restrict__ ln1b) {
    int lane = threadIdx.x & 31;
    int warp = threadIdx.x >> 5;
    int sub = lane >> 4;
    int sl = lane & 15;
    int gp = blockIdx.x * 16 + warp * 2 + sub;
    int b = gp >> 14;
    int p = gp & (Pp - 1);

    float us[6], vs[6];
#pragma unroll
    for (int n = 0; n < 6; n++) {
        int bn = b * Nn + n;
        us[n] = homo[(size_t)(bn * 2 + 0) * Pp + p] * 128.0f;
        vs[n] = homo[(size_t)(bn * 2 + 1) * Pp + p] * 128.0f;
    }

    float q[8];
    {
        float4 q0 = *(const float4*)(qT_g + (size_t)gp * Dd + sl * 8);
        float4 q1 = *(const float4*)(qT_g + (size_t)gp * Dd + sl * 8 + 4);
        q[0] = q0.x; q[1] = q0.y; q[2] = q0.z; q[3] = q0.w;
        q[4] = q1.x; q[5] = q1.y; q[6] = q1.z; q[7] = q1.w;
    }
    float qn2 = 0.0f;
#pragma unroll
    for (int k = 0; k < 8; k++) qn2 += q[k] * q[k];
    qn2 = wsum16(qn2);
    float qden = fmaxf(sqrtf(qn2), 1e-12f);

    __half2 vh[6][4];
    float dots[6];

#pragma unroll
    for (int n = 0; n < 6; n++) {
        int bn = b * Nn + n;
        float u = us[n], v = vs[n];
        float wx = u - floorf(u), wy = v - floorf(v);
        int ix0 = min(max(__float2int_rd(u), 0), 127);
        int ix1 = min(max(__float2int_rd(u) + 1, 0), 127);
        int iy0 = min(max(__float2int_rd(v), 0), 127);
        int iy1 = min(max(__float2int_rd(v) + 1, 0), 127);
        bool valid = (u >= 0.0f) && (u <= 127.0f) && (v >= 0.0f) && (v <= 127.0f);

        const __half* base = refTh_g + (size_t)bn * Pp * Dd + sl * 8;
        uint4 r00 = *(const uint4*)(base + ((iy0 << 7) + ix0) * Dd);
        uint4 r10 = *(const uint4*)(base + ((iy0 << 7) + ix1) * Dd);
        uint4 r01 = *(const uint4*)(base + ((iy1 << 7) + ix0) * Dd);
        uint4 r11 = *(const uint4*)(base + ((iy1 << 7) + ix1) * Dd);

        float c00[8], c10[8], c01[8], c11[8];
        h8_to_f8(r00, c00); h8_to_f8(r10, c10);
        h8_to_f8(r01, c01); h8_to_f8(r11, c11);

        float w00 = (1.0f - wx) * (1.0f - wy);
        float w10 = wx * (1.0f - wy);
        float w01 = (1.0f - wx) * wy;
        float w11 = wx * wy;

        float v2 = 0.0f, s = 0.0f;
#pragma unroll
        for (int k = 0; k < 8; k += 2) {
            float val0 = w00 * c00[k] + w10 * c10[k] + w01 * c01[k] + w11 * c11[k];
            float val1 = w00 * c00[k + 1] + w10 * c10[k + 1] + w01 * c01[k + 1] + w11 * c11[k + 1];
            vh[n][k >> 1] = __floats2half2_rn(val0, val1);
            v2 += val0 * val0 + val1 * val1;
            s += q[k] * val0 + q[k + 1] * val1;
        }
        v2 = wsum16(v2);
        s = wsum16(s);
        float vden = fmaxf(sqrtf(v2), 1e-12f);
        dots[n] = valid ? __fdividef(s, qden * vden) : 0.0f;
    }

    float m = dots[0];
#pragma unroll
    for (int n = 1; n < 6; n++) m = fmaxf(m, dots[n]);
    float e[6], esum = 0.0f;
#pragma unroll
    for (int n = 0; n < 6; n++) { e[n] = __expf(dots[n] - m); esum += e[n]; }
    float inv = __fdividef(1.0f, esum);

#pragma unroll
    for (int k2 = 0; k2 < 4; k2++) {
        float zx = 0.0f, zy = 0.0f;
#pragma unroll
        for (int n = 0; n < 6; n++) {
            float2 vv = __half22float2(vh[n][k2]);
            zx += e[n] * vv.x;
            zy += e[n] * vv.y;
        }
        q[2 * k2] += zx * inv;
        q[2 * k2 + 1] += zy * inv;
    }

    float ssum = 0.0f;
#pragma unroll
    for (int k = 0; k < 8; k++) ssum += q[k];
    float mean = wsum16(ssum) * (1.0f / 128.0f);
    float dv = 0.0f;
#pragma unroll
    for (int k = 0; k < 8; k++) { float dd = q[k] - mean; dv += dd * dd; }
    float rstd = rsqrtf(wsum16(dv) * (1.0f / 128.0f) + 1e-5f);

    float o[8];
    {
        float4 lw0 = *(const float4*)(ln1w + sl * 8);
        float4 lw1 = *(const float4*)(ln1w + sl * 8 + 4);
        float4 lb0 = *(const float4*)(ln1b + sl * 8);
        float4 lb1 = *(const float4*)(ln1b + sl * 8 + 4);
        o[0] = (q[0] - mean) * rstd * lw0.x + lb0.x;
        o[1] = (q[1] - mean) * rstd * lw0.y + lb0.y;
        o[2] = (q[2] - mean) * rstd * lw0.z + lb0.z;
        o[3] = (q[3] - mean) * rstd * lw0.w + lb0.w;
        o[4] = (q[4] - mean) * rstd * lw1.x + lb1.x;
        o[5] = (q[5] - mean) * rstd * lw1.y + lb1.y;
        o[6] = (q[6] - mean) * rstd * lw1.z + lb1.z;
        o[7] = (q[7] - mean) * rstd * lw1.w + lb1.w;
    }
    float* dstf = ztLN_g + (size_t)gp * Dd + sl * 8;
    *(float4*)dstf = make_float4(o[0], o[1], o[2], o[3]);
    *(float4*)(dstf + 4) = make_float4(o[4], o[5], o[6], o[7]);

    __half2 h[4];
    h[0] = __floats2half2_rn(o[0], o[1]);
    h[1] = __floats2half2_rn(o[2], o[3]);
    h[2] = __floats2half2_rn(o[4], o[5]);
    h[3] = __floats2half2_rn(o[6], o[7]);
    *(float4*)(ztLNh_g + (size_t)gp * Dd + sl * 8) = *(float4*)h;
}

// ---------------------------------------------------------------
// Fused MLP (mma.sync, BM=64): out = LN2(ztLN + gelu(ztLNh@W1+b1)@W2 + b2)
// H kept in smem; weights streamed through one 34.8KB buffer.
// smem 89KB, ~90 regs -> 2 CTAs/SM.
// ---------------------------------------------------------------
#define AIN_OFF  0
#define H0_OFF   (64 * APITCH)
#define H1_OFF   (128 * APITCH)
#define W_OFF    (192 * APITCH)
#define RED_OFF  (320 * APITCH)
#define MLP_SMEM (320 * APITCH * 2 + 2048)   // 89088 bytes
#define STGP 68   // float stride for staging [128][STGP] (reuses Ain+H0 = 8704 floats)
__global__ void __launch_bounds__(256) mlp_mma(const float* __restrict__ b1,
                                               const float* __restrict__ b2,
                                               const float* __restrict__ ln2w,
                                               const float* __restrict__ ln2b,
                                               float* __restrict__ out) {
    extern __shared__ __half sm[];
    __half* Ain = sm + AIN_OFF;
    __half* H0  = sm + H0_OFF;
    __half* H1  = sm + H1_OFF;
    __half* Wb  = sm + W_OFF;
    float* redS = (float*)(sm + RED_OFF);   // [64][4]
    float* redQ = redS + 256;               // [64][4]
    float* stg  = (float*)sm;               // [128][STGP] reuses Ain+H0
    uint32_t Abase = smem_u32(Ain);
    uint32_t H0b = smem_u32(H0), H1b = smem_u32(H1);
    uint32_t Wbase = smem_u32(Wb);

    int tid = threadIdx.x;
    int warp = tid >> 5, lane = tid & 31;
    int rowBase = blockIdx.x * 64;

    int warp_m = warp & 1, warp_n = warp >> 1;
    int rm = warp_m * 32, cn = warp_n * 32;
    int arow = (lane & 7) + ((lane >> 3) & 1) * 8;
    int akol = (lane >> 4) * 8;
    int brow = lane & 7;
    int bkol = ((lane >> 3) & 1) * 8;
    int qrow = lane >> 2, qcol = (lane & 3) * 2;

    // fill Ain (64x128 from ztLNh) + W = W1 n-half0
    for (int idx = tid; idx < 1024; idx += 256) {
        int r = idx >> 4, kg = (idx & 15) << 3;
        *(float4*)(Ain + r * APITCH + kg) =
            *(const float4*)(ztLNh_g + (size_t)(rowBase + r) * 128 + kg);
    }
    for (int idx = tid; idx < 2048; idx += 256) {
        int r = idx >> 4, kg = (idx & 15) << 3;
        *(float4*)(Wb + r * APITCH + kg) =
            *(const float4*)(W1h_g + (size_t)r * 128 + kg);
    }
    __syncthreads();

    // ---- Phase 1: H = gelu(A @ W1 + b1), two n-halves ----
#pragma unroll
    for (int nh = 0; nh < 2; nh++) {
        float acc[2][4][4] = {};
#pragma unroll
        for (int ks = 0; ks < 8; ks++) {
            int k0 = ks * 16;
            uint32_t a[2][4], bf[4][2];
#pragma unroll
            for (int mt = 0; mt < 2; mt++)
                LDSM_X4(a[mt][0], a[mt][1], a[mt][2], a[mt][3],
                        Abase + ((rm + mt * 16 + arow) * APITCH + k0 + akol) * 2);
#pragma unroll
            for (int nt = 0; nt < 4; nt++)
                LDSM_X2(bf[nt][0], bf[nt][1],
                        Wbase + ((cn + nt * 8 + brow) * APITCH + k0 + bkol) * 2);
#pragma unroll
            for (int mt = 0; mt < 2; mt++)
#pragma unroll
                for (int nt = 0; nt < 4; nt++)
                    MMA16816(acc[mt][nt], a[mt], bf[nt]);
        }

        // gelu + bias -> H smem (row x col, APITCH layout)
        __half* Hd = nh ? H1 : H0;
#pragma unroll
        for (int nt = 0; nt < 4; nt++) {
            int col = cn + nt * 8 + qcol;
            int gcol = nh * 128 + col;
            float bx = __ldg(b1 + gcol), by = __ldg(b1 + gcol + 1);
#pragma unroll
            for (int mt = 0; mt < 2; mt++) {
                int row = rm + mt * 16 + qrow;
                *(__half2*)(Hd + row * APITCH + col) =
                    __floats2half2_rn(gelu_exact(acc[mt][nt][0] + bx),
                                      gelu_exact(acc[mt][nt][1] + by));
                *(__half2*)(Hd + (row + 8) * APITCH + col) =
                    __floats2half2_rn(gelu_exact(acc[mt][nt][2] + bx),
                                      gelu_exact(acc[mt][nt][3] + by));
            }
        }

        // refill W: nh==0 -> W1 half1 ; nh==1 -> W2 k-chunk0
        __syncthreads();
        if (nh == 0) {
            for (int idx = tid; idx < 2048; idx += 256) {
                int r = idx >> 4, kg = (idx & 15) << 3;
                *(float4*)(Wb + r * APITCH + kg) =
                    *(const float4*)(W1h_g + (size_t)(128 + r) * 128 + kg);
            }
        } else {
            for (int idx = tid; idx < 2048; idx += 256) {
                int r = idx >> 4, kg = (idx & 15) << 3;
                *(float4*)(Wb + r * APITCH + kg) =
                    *(const float4*)(W2h_g + (size_t)r * 256 + kg);
            }
        }
        __syncthreads();
    }

    // ---- Phase 2: Z = H @ W2, K=256 in two chunks ----
    float acc[2][4][4] = {};
#pragma unroll
    for (int kc = 0; kc < 2; kc++) {
        uint32_t Hb_ = kc ? H1b : H0b;
#pragma unroll
        for (int ks = 0; ks < 8; ks++) {
            int k0 = ks * 16;
            uint32_t a[2][4], bf[4][2];
#pragma unroll
            for (int mt = 0; mt < 2; mt++)
                LDSM_X4(a[mt][0], a[mt][1], a[mt][2], a[mt][3],
                        Hb_ + ((rm + mt * 16 + arow) * APITCH + k0 + akol) * 2);
#pragma unroll
            for (int nt = 0; nt < 4; nt++)
                LDSM_X2(bf[nt][0], bf[nt][1],
                        Wbase + ((cn + nt * 8 + brow) * APITCH + k0 + bkol) * 2);
#pragma unroll
            for (int mt = 0; mt < 2; mt++)
#pragma unroll
                for (int nt = 0; nt < 4; nt++)
                    MMA16816(acc[mt][nt], a[mt], bf[nt]);
        }
        if (kc == 0) {
            __syncthreads();   // W2 chunk0 reads done
            for (int idx = tid; idx < 2048; idx += 256) {
                int r = idx >> 4, kg = (idx & 15) << 3;
                *(float4*)(Wb + r * APITCH + kg) =
                    *(const float4*)(W2h_g + (size_t)r * 256 + 128 + kg);
            }
            __syncthreads();
        }
    }

    // ---- Epilogue: residual + bias; LN2; transposed store ----
#pragma unroll
    for (int mt = 0; mt < 2; mt++) {
        int rlo = rm + mt * 16 + qrow;
        int rhi = rlo + 8;
        float sLo = 0.0f, qLo = 0.0f, sHi = 0.0f, qHi = 0.0f;
#pragma unroll
        for (int nt = 0; nt < 4; nt++) {
            int col = cn + nt * 8 + qcol;
            float bx = __ldg(b2 + col), by = __ldg(b2 + col + 1);
            float2 zlo = *(const float2*)(ztLN_g + (size_t)(rowBase + rlo) * 128 + col);
            float2 zhi = *(const float2*)(ztLN_g + (size_t)(rowBase + rhi) * 128 + col);
            acc[mt][nt][0] += zlo.x + bx;
            acc[mt][nt][1] += zlo.y + by;
            acc[mt][nt][2] += zhi.x + bx;
            acc[mt][nt][3] += zhi.y + by;
            sLo += acc[mt][nt][0] + acc[mt][nt][1];
            qLo += acc[mt][nt][0] * acc[mt][nt][0] + acc[mt][nt][1] * acc[mt][nt][1];
            sHi += acc[mt][nt][2] + acc[mt][nt][3];
            qHi += acc[mt][nt][2] * acc[mt][nt][2] + acc[mt][nt][3] * acc[mt][nt][3];
        }
#pragma unroll
        for (int sh = 1; sh < 4; sh <<= 1) {
            sLo += __shfl_xor_sync(0xffffffffu, sLo, sh);
            qLo += __shfl_xor_sync(0xffffffffu, qLo, sh);
            sHi += __shfl_xor_sync(0xffffffffu, sHi, sh);
            qHi += __shfl_xor_sync(0xffffffffu, qHi, sh);
        }
        if ((lane & 3) == 0) {
            redS[rlo * 4 + warp_n] = sLo;
            redQ[rlo * 4 + warp_n] = qLo;
            redS[rhi * 4 + warp_n] = sHi;
            redQ[rhi * 4 + warp_n] = qHi;
        }
    }
    __syncthreads();   // red ready; H0/W reads done -> stg may overwrite Ain+H0

#pragma unroll
    for (int mt = 0; mt < 2; mt++) {
        int rlo = rm + mt * 16 + qrow;
        int rhi = rlo + 8;
        float sLo = redS[rlo * 4 + 0] + redS[rlo * 4 + 1] + redS[rlo * 4 + 2] + redS[rlo * 4 + 3];
        float qLo = redQ[rlo * 4 + 0] + redQ[rlo * 4 + 1] + redQ[rlo * 4 + 2] + redQ[rlo * 4 + 3];
        float sHi = redS[rhi * 4 + 0] + redS[rhi * 4 + 1] + redS[rhi * 4 + 2] + redS[rhi * 4 + 3];
        float qHi = redQ[rhi * 4 + 0] + redQ[rhi * 4 + 1] + redQ[rhi * 4 + 2] + redQ[rhi * 4 + 3];
        float mLo = sLo * (1.0f / 128.0f);
        float rLo = rsqrtf(qLo * (1.0f / 128.0f) - mLo * mLo + 1e-5f);
        float mHi = sHi * (1.0f / 128.0f);
        float rHi = rsqrtf(qHi * (1.0f / 128.0f) - mHi * mHi + 1e-5f);
#pragma unroll
        for (int nt = 0; nt < 4; nt++) {
            int col = cn + nt * 8 + qcol;
            float lwx = __ldg(ln2w + col), lwy = __ldg(ln2w + col + 1);
            float lbx = __ldg(ln2b + col), lby = __ldg(ln2b + col + 1);
            stg[(col + 0) * STGP + rlo] = (acc[mt][nt][0] - mLo) * rLo * lwx + lbx;
            stg[(col + 1) * STGP + rlo] = (acc[mt][nt][1] - mLo) * rLo * lwy + lby;
            stg[(col + 0) * STGP + rhi] = (acc[mt][nt][2] - mHi) * rHi * lwx + lbx;
            stg[(col + 1) * STGP + rhi] = (acc[mt][nt][3] - mHi) * rHi * lwy + lby;
        }
    }
    __syncthreads();

    int b = rowBase >> 14;
    int prowBase = rowBase & (Pp - 1);
    for (int idx = tid; idx < 2048; idx += 256) {
        int c = idx >> 4;
        int j = (idx & 15) * 4;
        float4 v = *(const float4*)(stg + c * STGP + j);
        *(float4*)(out + ((size_t)(b * 128 + c)) * Pp + prowBase + j) = v;
    }
}

// ---------------------------------------------------------------
extern "C" void kernel_launch(void* const* d_in, const int* in_sizes, int n_in,
                              void* d_out, int out_size) {
    const float* query = (const float*)d_in[0];
    const float* ref   = (const float*)d_in[1];
    const float* homo  = (const float*)d_in[2];
    const float* ln1w  = (const float*)d_in[3];
    const float* ln1b  = (const float*)d_in[4];
    const float* ln2w  = (const float*)d_in[5];
    const float* ln2b  = (const float*)d_in[6];
    const float* w1    = (const float*)d_in[7];
    const float* b1    = (const float*)d_in[8];
    const float* w2    = (const float*)d_in[9];
    const float* b2    = (const float*)d_in[10];
    float* out = (float*)d_out;

    cudaFuncSetAttribute(mlp_mma, cudaFuncAttributeMaxDynamicSharedMemorySize, MLP_SMEM);

    prep_all_kernel<<<dim3(Pp / 32, 1, 29), 256>>>(ref, query, w1, w2);
    attn_kernel<<<Mm / 16, 256>>>(homo, ln1w, ln1b);
    mlp_mma<<<Mm / 64, 256, MLP_SMEM>>>(b1, b2, ln2w, ln2b, out);
}